// round 7
// baseline (speedup 1.0000x reference)
#include <cuda_runtime.h>
#include <math.h>

#define HW 224
#define C 96
#define T 49
#define CQKV 288
#define HID 384
#define HCH 192

#define XSTR 96
#define QSTR 98
#define KSTR 98
#define VSTR 96
#define SSTR 52
#define HSTR 192
#define WSTR 292
#define W1STR 196
#define W2STR 100

#define OFF_Q 4704            /* 49*96, 16B aligned */
#define OFF_K 9508            /* padded to mult of 4 floats */
#define OFF_V 14312           /* padded to mult of 4 floats */
#define SMEM_FLOATS (OFF_V + 50*VSTR)   /* 19112 */
#define SMEM_BYTES (SMEM_FLOATS * 4)    /* 76448 -> 3 CTAs/SM */

typedef unsigned long long u64t;

__device__ __forceinline__ u64t splat2(float a){
    u64t r; asm("mov.b64 %0, {%1,%1};" : "=l"(r) : "f"(a)); return r;
}
__device__ __forceinline__ u64t pk2(float a, float b){
    u64t r; asm("mov.b64 %0, {%1,%2};" : "=l"(r) : "f"(a), "f"(b)); return r;
}
__device__ __forceinline__ u64t fma2(u64t a, u64t b, u64t c){
    u64t d; asm("fma.rn.f32x2 %0, %1, %2, %3;" : "=l"(d) : "l"(a), "l"(b), "l"(c)); return d;
}
__device__ __forceinline__ void up2(u64t x, float& l, float& h){
    asm("mov.b64 {%0,%1}, %2;" : "=f"(l), "=f"(h) : "l"(x));
}

__global__ __launch_bounds__(256, 3)
void swin_fused(const float* __restrict__ x, const float* __restrict__ qkv_w,
                const float* __restrict__ ln_w, const float* __restrict__ ln_b,
                const float* __restrict__ w1, const float* __restrict__ b1,
                const float* __restrict__ w2, const float* __restrict__ b2,
                float* __restrict__ out)
{
    extern __shared__ float sm[];
    float* XLN = sm;                 // [49][96]; later S; later w2 staging
    float* Qs  = sm + OFF_Q;         // QKV staging during sweep; then Q; then attn_out
    float* Ks  = sm + OFF_K;         // w1 staging during sweep; K
    float* Vs  = sm + OFF_V;         // [50][96] (row 49 zeroed)
    float* Ss  = sm;                 // [49][52] overlays XLN
    float* HB  = sm + OFF_K;         // hidden [50][192] overlays K+V

    const int tid  = threadIdx.x;
    const int widx = blockIdx.x;
    const int b  = widx >> 10;
    const int wh = (widx >> 5) & 31;
    const int ww = widx & 31;
    const size_t base = ((size_t)(b*HW + wh*7) * HW + (size_t)(ww*7)) * C;

    // ---- load x window (49 x 96) ----
    for (int i = tid; i < T*24; i += 256) {
        int t = i / 24, v4 = i - t*24;
        int r = t / 7, s = t - r*7;
        float4 val = *(const float4*)(x + base + (size_t)(r*HW + s)*C + v4*4);
        *(float4*)(XLN + t*XSTR + v4*4) = val;
    }
    __syncthreads();

    // ---- layernorm ----
    {
        const int lane = tid & 31, warp = tid >> 5;
        const float lw0 = ln_w[lane], lw1 = ln_w[lane+32], lw2 = ln_w[lane+64];
        const float lb0 = ln_b[lane], lb1 = ln_b[lane+32], lb2 = ln_b[lane+64];
        for (int t = warp; t < T; t += 8) {
            float a0 = XLN[t*XSTR+lane], a1 = XLN[t*XSTR+lane+32], a2 = XLN[t*XSTR+lane+64];
            float sum = a0+a1+a2;
            float sq  = a0*a0 + a1*a1 + a2*a2;
            #pragma unroll
            for (int o = 16; o; o >>= 1) {
                sum += __shfl_xor_sync(0xffffffffu, sum, o);
                sq  += __shfl_xor_sync(0xffffffffu, sq , o);
            }
            float mu  = sum * (1.f/96.f);
            float var = fmaxf(sq * (1.f/96.f) - mu*mu, 0.f);
            float rs  = rsqrtf(var + 1e-5f);
            XLN[t*XSTR+lane]    = (a0-mu)*rs*lw0 + lb0;
            XLN[t*XSTR+lane+32] = (a1-mu)*rs*lw1 + lb1;
            XLN[t*XSTR+lane+64] = (a2-mu)*rs*lw2 + lb2;
        }
    }
    __syncthreads();

    // ---- QKV GEMM: staged weights in Q region (dead during sweep) ----
    {
        float* Wst = Qs;                            // 16 x 292 <= 49*98
        const int cg = tid % 36, tg = tid / 36;     // tg<7 valid
        const int trow = (tg < 7 ? tg : 6) * 7;
        u64t acc[7][4];
        #pragma unroll
        for (int i=0;i<7;i++)
            #pragma unroll
            for (int p=0;p<4;p++) acc[i][p] = 0ull;
        for (int c0 = 0; c0 < C; c0 += 16) {
            for (int i = tid; i < 1152; i += 256) {            // 16 rows x 288 cols
                int cc = i / 72, j4 = i - cc*72;
                *(float4*)(Wst + cc*WSTR + j4*4) =
                    *(const float4*)(qkv_w + (size_t)(c0+cc)*CQKV + j4*4);
            }
            __syncthreads();
            #pragma unroll 4
            for (int cc = 0; cc < 16; cc++) {
                const u64t* wp = (const u64t*)(Wst + cc*WSTR + cg*8);
                u64t w0=wp[0], w1v=wp[1], w2v=wp[2], w3v=wp[3];
                #pragma unroll
                for (int i=0;i<7;i++) {
                    u64t xs = splat2(XLN[(trow+i)*XSTR + c0 + cc]);
                    acc[i][0] = fma2(xs, w0, acc[i][0]);
                    acc[i][1] = fma2(xs, w1v, acc[i][1]);
                    acc[i][2] = fma2(xs, w2v, acc[i][2]);
                    acc[i][3] = fma2(xs, w3v, acc[i][3]);
                }
            }
            __syncthreads();
        }
        // staging dead; write Q/K/V
        if (tg < 7) {
            const int j0 = cg*8;
            float* dst; int jl; int str;
            if (j0 < 96)       { dst = Qs; jl = j0;        str = QSTR; }
            else if (j0 < 192) { dst = Ks; jl = j0 - 96;   str = KSTR; }
            else               { dst = Vs; jl = j0 - 192;  str = VSTR; }
            #pragma unroll
            for (int i=0;i<7;i++)
                #pragma unroll
                for (int p=0;p<4;p++) {
                    float l,h; up2(acc[i][p], l, h);
                    dst[(tg*7+i)*str + jl + 2*p]   = l;
                    dst[(tg*7+i)*str + jl + 2*p+1] = h;
                }
        }
    }
    if (tid < 48) *(u64t*)(Vs + 49*VSTR + tid*2) = 0ull;   // zero V row 49
    __syncthreads();

    // ---- logits S = Q K^T / sqrt(96) (into XLN region) ----
    {
        const float scale = 0.10206207261596577f;
        for (int u = tid; u < 343; u += 256) {
            int n = u / 7, mg = u - n*7;
            u64t a2[7];
            #pragma unroll
            for (int mm=0;mm<7;mm++) a2[mm] = 0ull;
            #pragma unroll 4
            for (int c = 0; c < C; c += 4) {
                const u64t* qp = (const u64t*)(Qs + n*QSTR + c);
                u64t q0 = qp[0], q1 = qp[1];
                #pragma unroll
                for (int mm=0;mm<7;mm++) {
                    const u64t* kp = (const u64t*)(Ks + (mg*7+mm)*KSTR + c);
                    a2[mm] = fma2(q0, kp[0], a2[mm]);
                    a2[mm] = fma2(q1, kp[1], a2[mm]);
                }
            }
            #pragma unroll
            for (int mm=0;mm<7;mm++) {
                float l,h; up2(a2[mm], l, h);
                Ss[n*SSTR + mg*7+mm] = (l+h)*scale;
            }
        }
    }
    __syncthreads();

    // ---- softmax rows (+ zero pad col 49) ----
    {
        const int lane = tid & 31, warp = tid >> 5;
        for (int n = warp; n < T; n += 8) {
            float v0 = Ss[n*SSTR + lane];
            float v1 = (lane < 17) ? Ss[n*SSTR + 32 + lane] : -3.0e38f;
            float m = fmaxf(v0, v1);
            #pragma unroll
            for (int o=16;o;o>>=1) m = fmaxf(m, __shfl_xor_sync(0xffffffffu, m, o));
            float e0 = __expf(v0 - m);
            float e1 = (lane < 17) ? __expf(v1 - m) : 0.f;
            float ssum = e0 + e1;
            #pragma unroll
            for (int o=16;o;o>>=1) ssum += __shfl_xor_sync(0xffffffffu, ssum, o);
            float inv = 1.f / ssum;
            Ss[n*SSTR + lane] = e0*inv;
            if (lane < 17) Ss[n*SSTR + 32 + lane] = e1*inv;
            if (lane == 17) Ss[n*SSTR + 49] = 0.f;
        }
    }
    __syncthreads();

    // ---- attn_out = S @ V -> Q region ----
    {
        const int cg = tid % 24, tg = tid / 24;   // tg<10, 5 rows each
        if (tg < 10) {
            u64t acc[5][4];
            #pragma unroll
            for (int i=0;i<5;i++)
                #pragma unroll
                for (int p=0;p<4;p++) acc[i][p] = 0ull;
            #pragma unroll 5
            for (int m = 0; m < 50; m += 2) {
                float4 va = *(float4*)(Vs + m*VSTR + cg*4);
                float4 vb = *(float4*)(Vs + (m+1)*VSTR + cg*4);
                u64t v0 = pk2(va.x, vb.x), v1 = pk2(va.y, vb.y);
                u64t v2 = pk2(va.z, vb.z), v3 = pk2(va.w, vb.w);
                #pragma unroll
                for (int i=0;i<5;i++) {
                    u64t s2 = *(const u64t*)(Ss + (tg*5+i)*SSTR + m);
                    acc[i][0] = fma2(s2, v0, acc[i][0]);
                    acc[i][1] = fma2(s2, v1, acc[i][1]);
                    acc[i][2] = fma2(s2, v2, acc[i][2]);
                    acc[i][3] = fma2(s2, v3, acc[i][3]);
                }
            }
            #pragma unroll
            for (int i=0;i<5;i++) {
                int t = tg*5 + i;
                float l0,h0,l1,h1,l2,h2,l3,h3;
                up2(acc[i][0], l0, h0); up2(acc[i][1], l1, h1);
                up2(acc[i][2], l2, h2); up2(acc[i][3], l3, h3);
                u64t* d = (u64t*)(Qs + t*QSTR + cg*4);
                d[0] = pk2(l0+h0, l1+h1);
                d[1] = pk2(l2+h2, l3+h3);
            }
        }
    }
    __syncthreads();

    // ---- MLP ----
    const int cg6 = tid % 32, tg8 = tid / 32;      // w1 map: 6 cols x 7 rows
    const int cgf = tid % 24, tgf = tid / 24;      // w2 map: 4 cols x 5 rows (tgf<10)
    const int trow1 = (tg8 < 7 ? tg8 : 6) * 7;
    u64t facc[5][2];
    #pragma unroll
    for (int i=0;i<5;i++){ facc[i][0]=0ull; facc[i][1]=0ull; }

    for (int hc = 0; hc < 2; hc++) {
        const int j0 = hc * HCH;
        // --- hidden = gelu(attn_out @ w1[:, j0:j0+192] + b1), staged in K region ---
        {
            float* Wst = Ks;                       // 16 x 196 <= 49*98 (dead during sweep)
            u64t hacc[7][3];
            #pragma unroll
            for (int i=0;i<7;i++){ hacc[i][0]=0ull; hacc[i][1]=0ull; hacc[i][2]=0ull; }
            for (int c0 = 0; c0 < C; c0 += 16) {
                for (int i = tid; i < 768; i += 256) {         // 16 rows x 192 cols
                    int cc = i / 48, j4 = i - cc*48;
                    *(float4*)(Wst + cc*W1STR + j4*4) =
                        *(const float4*)(w1 + (size_t)(c0+cc)*HID + j0 + j4*4);
                }
                __syncthreads();
                #pragma unroll 4
                for (int cc=0;cc<16;cc++) {
                    const u64t* wp = (const u64t*)(Wst + cc*W1STR + cg6*6);
                    u64t w0=wp[0], w1v=wp[1], w2v=wp[2];
                    #pragma unroll
                    for (int i=0;i<7;i++) {
                        u64t xs = splat2(Qs[(trow1+i)*QSTR + c0+cc]);
                        hacc[i][0] = fma2(xs, w0, hacc[i][0]);
                        hacc[i][1] = fma2(xs, w1v, hacc[i][1]);
                        hacc[i][2] = fma2(xs, w2v, hacc[i][2]);
                    }
                }
                __syncthreads();
            }
            if (tg8 < 7) {
                const float* bp = b1 + j0 + cg6*6;
                float bv[6];
                #pragma unroll
                for (int j=0;j<6;j++) bv[j] = bp[j];
                #pragma unroll
                for (int i=0;i<7;i++) {
                    float* hrow = HB + (tg8*7+i)*HSTR + cg6*6;
                    #pragma unroll
                    for (int p=0;p<3;p++) {
                        float l,h; up2(hacc[i][p], l, h);
                        float h0 = l + bv[2*p];
                        float h1 = h + bv[2*p+1];
                        hrow[2*p]   = 0.5f*h0*(1.f + erff(h0*0.70710678118654752f));
                        hrow[2*p+1] = 0.5f*h1*(1.f + erff(h1*0.70710678118654752f));
                    }
                }
            }
            if (tid < 96) *(u64t*)(HB + 49*HSTR + tid*2) = 0ull;
        }
        __syncthreads();
        // --- facc += hidden @ w2[j0:j0+192, :], staged in XLN/S region ---
        {
            float* Wst = sm;                       // 32 x 100 <= 4704 (S dead now)
            for (int k0 = 0; k0 < HCH; k0 += 32) {
                for (int i = tid; i < 768; i += 256) {         // 32 rows x 96 cols
                    int kk = i / 24, c4 = i - kk*24;
                    *(float4*)(Wst + kk*W2STR + c4*4) =
                        *(const float4*)(w2 + (size_t)(j0+k0+kk)*C + c4*4);
                }
                __syncthreads();
                if (tgf < 10) {
                    #pragma unroll 4
                    for (int kk=0;kk<32;kk++) {
                        const u64t* wp = (const u64t*)(Wst + kk*W2STR + cgf*4);
                        u64t w0=wp[0], w1v=wp[1];
                        #pragma unroll
                        for (int i=0;i<5;i++) {
                            u64t hs = splat2(HB[(tgf*5+i)*HSTR + k0+kk]);
                            facc[i][0] = fma2(hs, w0, facc[i][0]);
                            facc[i][1] = fma2(hs, w1v, facc[i][1]);
                        }
                    }
                }
                __syncthreads();
            }
        }
    }

    // ---- epilogue: + b2 + residual(attn_out), store ----
    if (tgf < 10) {
        float4 bb = *(const float4*)(b2 + cgf*4);
        #pragma unroll
        for (int i=0;i<5;i++) {
            int t = tgf*5 + i;
            if (t < 49) {
                int r = t / 7, s = t - r*7;
                const float* ao = Qs + t*QSTR + cgf*4;
                float l0,h0,l1,h1;
                up2(facc[i][0], l0, h0);
                up2(facc[i][1], l1, h1);
                float4 o;
                o.x = l0 + bb.x + ao[0];
                o.y = h0 + bb.y + ao[1];
                o.z = l1 + bb.z + ao[2];
                o.w = h1 + bb.w + ao[3];
                *(float4*)(out + base + (size_t)(r*HW + s)*C + cgf*4) = o;
            }
        }
    }
}

extern "C" void kernel_launch(void* const* d_in, const int* in_sizes, int n_in,
                              void* d_out, int out_size) {
    cudaFuncSetAttribute(swin_fused, cudaFuncAttributeMaxDynamicSharedMemorySize, SMEM_BYTES);
    swin_fused<<<8192, 256, SMEM_BYTES>>>(
        (const float*)d_in[0], (const float*)d_in[1], (const float*)d_in[2],
        (const float*)d_in[3], (const float*)d_in[4], (const float*)d_in[5],
        (const float*)d_in[6], (const float*)d_in[7], (float*)d_out);
}

// round 9
// speedup vs baseline: 1.5461x; 1.5461x over previous
#include <cuda_runtime.h>
#include <math.h>

#define HW 224
#define C 96
#define T 49
#define CQKV 288
#define HID 384
#define HCH 192

#define XSTR 96
#define QSTR 98
#define KSTR 98
#define VSTR 96
#define SSTR 52
#define HSTR 192
#define WSTR 292
#define W1STR 196
#define W2STR 100

#define OFF_Q 4704            /* 49*96 */
#define OFF_K 9508
#define OFF_V 14312
#define OFF_WST 19112         /* double-buffered staging */
#define WBUF 4672             /* 16*292 */
#define SMEM_FLOATS (OFF_WST + 2*WBUF)   /* 28456 */
#define SMEM_BYTES (SMEM_FLOATS * 4)     /* 113824 -> 2 CTAs/SM */

typedef unsigned long long u64t;

__device__ __forceinline__ u64t splat2(float a){
    u64t r; asm("mov.b64 %0, {%1,%1};" : "=l"(r) : "f"(a)); return r;
}
__device__ __forceinline__ u64t pk2(float a, float b){
    u64t r; asm("mov.b64 %0, {%1,%2};" : "=l"(r) : "f"(a), "f"(b)); return r;
}
__device__ __forceinline__ u64t fma2(u64t a, u64t b, u64t c){
    u64t d; asm("fma.rn.f32x2 %0, %1, %2, %3;" : "=l"(d) : "l"(a), "l"(b), "l"(c)); return d;
}
__device__ __forceinline__ void up2(u64t x, float& l, float& h){
    asm("mov.b64 {%0,%1}, %2;" : "=f"(l), "=f"(h) : "l"(x));
}

__global__ __launch_bounds__(256, 2)
void swin_fused(const float* __restrict__ x, const float* __restrict__ qkv_w,
                const float* __restrict__ ln_w, const float* __restrict__ ln_b,
                const float* __restrict__ w1, const float* __restrict__ b1,
                const float* __restrict__ w2, const float* __restrict__ b2,
                float* __restrict__ out)
{
    extern __shared__ float sm[];
    float* XLN = sm;                 // [49][96]; later S
    float* Qs  = sm + OFF_Q;         // Q; later attn_out
    float* Ks  = sm + OFF_K;         // K
    float* Vs  = sm + OFF_V;         // [50][96] (row 49 zeroed)
    float* Ss  = sm;                 // [49][52] overlays XLN
    float* HB  = sm + OFF_K;         // hidden [50][192] overlays K+V
    float* Wb0 = sm + OFF_WST;       // staging buffer 0
    float* Wb1 = Wb0 + WBUF;         // staging buffer 1

    const int tid  = threadIdx.x;
    const int widx = blockIdx.x;
    const int b  = widx >> 10;
    const int wh = (widx >> 5) & 31;
    const int ww = widx & 31;
    const size_t base = ((size_t)(b*HW + wh*7) * HW + (size_t)(ww*7)) * C;

    // ---- load x window (49 x 96) ----
    for (int i = tid; i < T*24; i += 256) {
        int t = i / 24, v4 = i - t*24;
        int r = t / 7, s = t - r*7;
        float4 val = *(const float4*)(x + base + (size_t)(r*HW + s)*C + v4*4);
        *(float4*)(XLN + t*XSTR + v4*4) = val;
    }
    __syncthreads();

    // ---- layernorm ----
    {
        const int lane = tid & 31, warp = tid >> 5;
        const float lw0 = ln_w[lane], lw1 = ln_w[lane+32], lw2 = ln_w[lane+64];
        const float lb0 = ln_b[lane], lb1 = ln_b[lane+32], lb2 = ln_b[lane+64];
        for (int t = warp; t < T; t += 8) {
            float a0 = XLN[t*XSTR+lane], a1 = XLN[t*XSTR+lane+32], a2 = XLN[t*XSTR+lane+64];
            float sum = a0+a1+a2;
            float sq  = a0*a0 + a1*a1 + a2*a2;
            #pragma unroll
            for (int o = 16; o; o >>= 1) {
                sum += __shfl_xor_sync(0xffffffffu, sum, o);
                sq  += __shfl_xor_sync(0xffffffffu, sq , o);
            }
            float mu  = sum * (1.f/96.f);
            float var = fmaxf(sq * (1.f/96.f) - mu*mu, 0.f);
            float rs  = rsqrtf(var + 1e-5f);
            XLN[t*XSTR+lane]    = (a0-mu)*rs*lw0 + lb0;
            XLN[t*XSTR+lane+32] = (a1-mu)*rs*lw1 + lb1;
            XLN[t*XSTR+lane+64] = (a2-mu)*rs*lw2 + lb2;
        }
        // preload QKV weight chunk 0 into buffer 0 (no conflict with LN rows)
        for (int i = tid; i < 1152; i += 256) {
            int cc = i / 72, j4 = i - cc*72;
            *(float4*)(Wb0 + cc*WSTR + j4*4) =
                *(const float4*)(qkv_w + (size_t)cc*CQKV + j4*4);
        }
    }
    __syncthreads();

    // ---- QKV GEMM: [49x96]@[96x288], double-buffered staging ----
    {
        const int cg = tid % 36, tg = tid / 36;     // tg<7 valid
        const int trow = (tg < 7 ? tg : 6) * 7;
        u64t acc[7][4];
        #pragma unroll
        for (int i=0;i<7;i++)
            #pragma unroll
            for (int p=0;p<4;p++) acc[i][p] = 0ull;
        #pragma unroll 1
        for (int ch = 0; ch < 6; ch++) {
            float* cur = (ch & 1) ? Wb1 : Wb0;
            float* nxt = (ch & 1) ? Wb0 : Wb1;
            if (ch < 5) {
                const int c0n = (ch+1)*16;
                for (int i = tid; i < 1152; i += 256) {
                    int cc = i / 72, j4 = i - cc*72;
                    *(float4*)(nxt + cc*WSTR + j4*4) =
                        *(const float4*)(qkv_w + (size_t)(c0n+cc)*CQKV + j4*4);
                }
            }
            const int c0 = ch*16;
            #pragma unroll 4
            for (int cc = 0; cc < 16; cc++) {
                const u64t* wp = (const u64t*)(cur + cc*WSTR + cg*8);
                u64t w0=wp[0], w1v=wp[1], w2v=wp[2], w3v=wp[3];
                #pragma unroll
                for (int i=0;i<7;i++) {
                    u64t xs = splat2(XLN[(trow+i)*XSTR + c0 + cc]);
                    acc[i][0] = fma2(xs, w0, acc[i][0]);
                    acc[i][1] = fma2(xs, w1v, acc[i][1]);
                    acc[i][2] = fma2(xs, w2v, acc[i][2]);
                    acc[i][3] = fma2(xs, w3v, acc[i][3]);
                }
            }
            __syncthreads();
        }
        if (tg < 7) {
            const int j0 = cg*8;
            float* dst; int jl; int str;
            if (j0 < 96)       { dst = Qs; jl = j0;        str = QSTR; }
            else if (j0 < 192) { dst = Ks; jl = j0 - 96;   str = KSTR; }
            else               { dst = Vs; jl = j0 - 192;  str = VSTR; }
            #pragma unroll
            for (int i=0;i<7;i++) {
                u64t* d = (u64t*)(dst + (tg*7+i)*str + jl);
                d[0]=acc[i][0]; d[1]=acc[i][1]; d[2]=acc[i][2]; d[3]=acc[i][3];
            }
        }
    }
    if (tid < 48) *(u64t*)(Vs + 49*VSTR + tid*2) = 0ull;   // zero V row 49
    __syncthreads();

    // ---- logits S = Q K^T / sqrt(96) ----
    {
        const float scale = 0.10206207261596577f;
        for (int u = tid; u < 343; u += 256) {
            int n = u / 7, mg = u - n*7;
            u64t a2[7];
            #pragma unroll
            for (int mm=0;mm<7;mm++) a2[mm] = 0ull;
            #pragma unroll 4
            for (int c = 0; c < C; c += 4) {
                const u64t* qp = (const u64t*)(Qs + n*QSTR + c);
                u64t q0 = qp[0], q1 = qp[1];
                #pragma unroll
                for (int mm=0;mm<7;mm++) {
                    const u64t* kp = (const u64t*)(Ks + (mg*7+mm)*KSTR + c);
                    a2[mm] = fma2(q0, kp[0], a2[mm]);
                    a2[mm] = fma2(q1, kp[1], a2[mm]);
                }
            }
            #pragma unroll
            for (int mm=0;mm<7;mm++) {
                float l,h; up2(a2[mm], l, h);
                Ss[n*SSTR + mg*7+mm] = (l+h)*scale;
            }
        }
    }
    __syncthreads();

    // ---- softmax rows (+ zero pad col 49) ----
    {
        const int lane = tid & 31, warp = tid >> 5;
        for (int n = warp; n < T; n += 8) {
            float v0 = Ss[n*SSTR + lane];
            float v1 = (lane < 17) ? Ss[n*SSTR + 32 + lane] : -3.0e38f;
            float m = fmaxf(v0, v1);
            #pragma unroll
            for (int o=16;o;o>>=1) m = fmaxf(m, __shfl_xor_sync(0xffffffffu, m, o));
            float e0 = __expf(v0 - m);
            float e1 = (lane < 17) ? __expf(v1 - m) : 0.f;
            float ssum = e0 + e1;
            #pragma unroll
            for (int o=16;o;o>>=1) ssum += __shfl_xor_sync(0xffffffffu, ssum, o);
            float inv = 1.f / ssum;
            Ss[n*SSTR + lane] = e0*inv;
            if (lane < 17) Ss[n*SSTR + 32 + lane] = e1*inv;
            if (lane == 17) Ss[n*SSTR + 49] = 0.f;
        }
    }
    __syncthreads();

    // ---- attn_out = S @ V -> Q region ----
    {
        const int cg = tid % 24, tg = tid / 24;
        if (tg < 10) {
            u64t acc[5][4];
            #pragma unroll
            for (int i=0;i<5;i++)
                #pragma unroll
                for (int p=0;p<4;p++) acc[i][p] = 0ull;
            #pragma unroll 5
            for (int m = 0; m < 50; m += 2) {
                float4 va = *(float4*)(Vs + m*VSTR + cg*4);
                float4 vb = *(float4*)(Vs + (m+1)*VSTR + cg*4);
                u64t v0 = pk2(va.x, vb.x), v1 = pk2(va.y, vb.y);
                u64t v2 = pk2(va.z, vb.z), v3 = pk2(va.w, vb.w);
                #pragma unroll
                for (int i=0;i<5;i++) {
                    u64t s2 = *(const u64t*)(Ss + (tg*5+i)*SSTR + m);
                    acc[i][0] = fma2(s2, v0, acc[i][0]);
                    acc[i][1] = fma2(s2, v1, acc[i][1]);
                    acc[i][2] = fma2(s2, v2, acc[i][2]);
                    acc[i][3] = fma2(s2, v3, acc[i][3]);
                }
            }
            #pragma unroll
            for (int i=0;i<5;i++) {
                int t = tg*5 + i;
                float l0,h0,l1,h1,l2,h2,l3,h3;
                up2(acc[i][0], l0, h0); up2(acc[i][1], l1, h1);
                up2(acc[i][2], l2, h2); up2(acc[i][3], l3, h3);
                u64t* d = (u64t*)(Qs + t*QSTR + cg*4);
                d[0] = pk2(l0+h0, l1+h1);
                d[1] = pk2(l2+h2, l3+h3);
            }
        }
        // preload w1 chunk 0 (half 0) into buffer 0
        for (int i = tid; i < 768; i += 256) {
            int cc = i / 48, j4 = i - cc*48;
            *(float4*)(Wb0 + cc*W1STR + j4*4) =
                *(const float4*)(w1 + (size_t)cc*HID + j4*4);
        }
    }
    __syncthreads();

    // ---- MLP ----
    const int cg6 = tid % 32, tg8 = tid / 32;      // w1 map: 6 cols x 7 rows
    const int cgf = tid % 24, tgf = tid / 24;      // w2 map: 4 cols x 5 rows (tgf<10)
    const int trow1 = (tg8 < 7 ? tg8 : 6) * 7;
    u64t facc[5][2];
    #pragma unroll
    for (int i=0;i<5;i++){ facc[i][0]=0ull; facc[i][1]=0ull; }

    #pragma unroll 1
    for (int hc = 0; hc < 2; hc++) {
        const int j0 = hc * HCH;
        // --- hidden = gelu(attn_out @ w1[:, j0:j0+192] + b1), DB staging ---
        // invariant: w1 chunk 0 of this half is already in Wb0
        {
            u64t hacc[7][3];
            #pragma unroll
            for (int i=0;i<7;i++){ hacc[i][0]=0ull; hacc[i][1]=0ull; hacc[i][2]=0ull; }
            #pragma unroll 1
            for (int ch = 0; ch < 6; ch++) {
                float* cur = (ch & 1) ? Wb1 : Wb0;
                float* nxt = (ch & 1) ? Wb0 : Wb1;
                if (ch < 5) {
                    const int c0n = (ch+1)*16;
                    for (int i = tid; i < 768; i += 256) {
                        int cc = i / 48, j4 = i - cc*48;
                        *(float4*)(nxt + cc*W1STR + j4*4) =
                            *(const float4*)(w1 + (size_t)(c0n+cc)*HID + j0 + j4*4);
                    }
                }
                const int c0 = ch*16;
                #pragma unroll 4
                for (int cc=0;cc<16;cc++) {
                    const u64t* wp = (const u64t*)(cur + cc*W1STR + cg6*6);
                    u64t w0=wp[0], w1v=wp[1], w2v=wp[2];
                    #pragma unroll
                    for (int i=0;i<7;i++) {
                        u64t xs = splat2(Qs[(trow1+i)*QSTR + c0+cc]);
                        hacc[i][0] = fma2(xs, w0, hacc[i][0]);
                        hacc[i][1] = fma2(xs, w1v, hacc[i][1]);
                        hacc[i][2] = fma2(xs, w2v, hacc[i][2]);
                    }
                }
                __syncthreads();
            }
            if (tg8 < 7) {
                const float* bp = b1 + j0 + cg6*6;
                float bv[6];
                #pragma unroll
                for (int j=0;j<6;j++) bv[j] = bp[j];
                #pragma unroll
                for (int i=0;i<7;i++) {
                    float* hrow = HB + (tg8*7+i)*HSTR + cg6*6;
                    #pragma unroll
                    for (int p=0;p<3;p++) {
                        float l,h; up2(hacc[i][p], l, h);
                        float h0 = l + bv[2*p];
                        float h1 = h + bv[2*p+1];
                        float g0 = 0.5f*h0*(1.f + erff(h0*0.70710678118654752f));
                        float g1 = 0.5f*h1*(1.f + erff(h1*0.70710678118654752f));
                        *(u64t*)(hrow + 2*p) = pk2(g0, g1);
                    }
                }
            }
            if (tid < 96) *(u64t*)(HB + 49*HSTR + tid*2) = 0ull;
            // preload w2 chunk 0 for this half into buffer 0
            // (Wb0 last read at w1 ch=4; synced since)
            for (int i = tid; i < 768; i += 256) {
                int kk = i / 24, c4 = i - kk*24;
                *(float4*)(Wb0 + kk*W2STR + c4*4) =
                    *(const float4*)(w2 + (size_t)(j0+kk)*C + c4*4);
            }
        }
        __syncthreads();
        // --- facc += hidden @ w2[j0:j0+192, :], DB staging ---
        {
            #pragma unroll 1
            for (int ch = 0; ch < 6; ch++) {
                float* cur = (ch & 1) ? Wb1 : Wb0;
                float* nxt = (ch & 1) ? Wb0 : Wb1;
                if (ch < 5) {
                    const int k0n = (ch+1)*32;
                    for (int i = tid; i < 768; i += 256) {
                        int kk = i / 24, c4 = i - kk*24;
                        *(float4*)(nxt + kk*W2STR + c4*4) =
                            *(const float4*)(w2 + (size_t)(j0+k0n+kk)*C + c4*4);
                    }
                } else if (hc == 0) {
                    // ch=5: nxt == Wb0. Preload w1 chunk 0 of half 1 into Wb0,
                    // exactly where hc=1's w1 loop (ch=0, cur=Wb0) expects it.
                    for (int i = tid; i < 768; i += 256) {
                        int cc = i / 48, j4 = i - cc*48;
                        *(float4*)(nxt + cc*W1STR + j4*4) =
                            *(const float4*)(w1 + (size_t)cc*HID + HCH + j4*4);
                    }
                }
                const int k0 = ch*32;
                if (tgf < 10) {
                    #pragma unroll 4
                    for (int kk=0;kk<32;kk++) {
                        const u64t* wp = (const u64t*)(cur + kk*W2STR + cgf*4);
                        u64t w0=wp[0], w1v=wp[1];
                        #pragma unroll
                        for (int i=0;i<5;i++) {
                            u64t hs = splat2(HB[(tgf*5+i)*HSTR + k0+kk]);
                            facc[i][0] = fma2(hs, w0, facc[i][0]);
                            facc[i][1] = fma2(hs, w1v, facc[i][1]);
                        }
                    }
                }
                __syncthreads();
            }
        }
        // no buffer swap: half-1 w1 chunk0 already lands in Wb0 (see above)
    }

    // ---- epilogue: + b2 + residual(attn_out), store ----
    if (tgf < 10) {
        float4 bb = *(const float4*)(b2 + cgf*4);
        #pragma unroll
        for (int i=0;i<5;i++) {
            int t = tgf*5 + i;
            if (t < 49) {
                int r = t / 7, s = t - r*7;
                const float* ao = Qs + t*QSTR + cgf*4;
                float l0,h0,l1,h1;
                up2(facc[i][0], l0, h0);
                up2(facc[i][1], l1, h1);
                float4 o;
                o.x = l0 + bb.x + ao[0];
                o.y = h0 + bb.y + ao[1];
                o.z = l1 + bb.z + ao[2];
                o.w = h1 + bb.w + ao[3];
                *(float4*)(out + base + (size_t)(r*HW + s)*C + cgf*4) = o;
            }
        }
    }
}

extern "C" void kernel_launch(void* const* d_in, const int* in_sizes, int n_in,
                              void* d_out, int out_size) {
    cudaFuncSetAttribute(swin_fused, cudaFuncAttributeMaxDynamicSharedMemorySize, SMEM_BYTES);
    swin_fused<<<8192, 256, SMEM_BYTES>>>(
        (const float*)d_in[0], (const float*)d_in[1], (const float*)d_in[2],
        (const float*)d_in[3], (const float*)d_in[4], (const float*)d_in[5],
        (const float*)d_in[6], (const float*)d_in[7], (float*)d_out);
}